// round 5
// baseline (speedup 1.0000x reference)
#include <cuda_runtime.h>
#include <cuda_bf16.h>

// Problem constants
#define NB 32            // N
#define MODES 4
#define EYS 192          // EY_SIZE
#define EY_PLANE (EYS*EYS)          // 36864 floats
#define EY_PLANE4 (EY_PLANE/4)      // 9216 float4
#define EYROW4 (EYS/4)              // 48 float4 per Ey row
#define TOTAL 1184       // (N + 2*KNN + 1) * OUT_RES
#define NK (NB*NB)       // 1024

// One thread per (row r, 4-column group). Round-2 inner loop (best measured).
// Weights computed inline from U/neff (uniform L1-hot loads, __fdividef).
// Grid remapped center-out in both dims so heavy interior CTAs launch first
// (straggler tail becomes light edge CTAs). 128-thread CTAs halve tail grain.
// blockDim = (32, 4); grid = (10, 296).
__global__ __launch_bounds__(128) void gather_en_kernel(
    const float* __restrict__ Ey,
    const float* __restrict__ U,
    const float* __restrict__ neff,
    float* __restrict__ out)
{
    // Center-out bijective remap: heavy (interior) tiles get low launch ids.
    const int gy = 296;
    int by = blockIdx.y;
    by = (by & 1) ? (gy / 2 - 1 - (by >> 1)) : (gy / 2 + (by >> 1));   // 0..295
    int bx = blockIdx.x;
    bx = (bx & 1) ? (4 - (bx >> 1)) : (5 + (bx >> 1));                 // 0..9

    const int lane = threadIdx.x;
    const int r    = by * 4 + threadIdx.y;             // 0..1183, uniform per warp
    const int c    = bx * 128 + lane * 4;              // 16B-aligned column
    const bool active = (c < TOTAL);

    // i-range uniform per warp
    int i_lo = (r - 160) >> 5; if (i_lo < 0) i_lo = 0;
    int i_hi = r >> 5;         if (i_hi > NB - 1) i_hi = NB - 1;

    // j-range per lane
    int j_lo = (c - 160) >> 5; if (j_lo < 0) j_lo = 0;
    int j_hi = c >> 5;         if (j_hi > NB - 1) j_hi = NB - 1;
    if (!active) { j_lo = 1; j_hi = 0; }               // no work for tail lanes

    const float4* __restrict__ U4   = reinterpret_cast<const float4*>(U);
    const float4* __restrict__ nf4  = reinterpret_cast<const float4*>(neff);
    const float4* __restrict__ Ey4  = reinterpret_cast<const float4*>(Ey);

    float4 acc = make_float4(0.f, 0.f, 0.f, 0.f);

    for (int i = i_lo; i <= i_hi; ++i) {
        const int x = r - (i << 5);                    // 0..191
        const long base_i = (long)(i << 5) * (MODES * EY_PLANE4) + (long)x * EYROW4;
        for (int j = j_lo; j <= j_hi; ++j) {
            const int k  = (i << 5) + j;
            const int y4 = (c - (j << 5)) >> 2;        // 0..47 float4 within row
            const float4* p = Ey4 + base_i + (long)j * (MODES * EY_PLANE4) + y4;

            // 4 independent streaming LDG.128s (the long-latency path)
            const float4 e0 = __ldg(p);
            const float4 e1 = __ldg(p + EY_PLANE4);
            const float4 e2 = __ldg(p + 2 * EY_PLANE4);
            const float4 e3 = __ldg(p + 3 * EY_PLANE4);

            // Inline weights: w = U * (n*1.5/(n+1.5)); uniform per warp, L1-hot
            const float4 u = __ldg(&U4[k]);
            const float4 n = __ldg(&nf4[k]);
            float4 wv;
            wv.x = u.x * __fdividef(n.x * 1.5f, n.x + 1.5f);
            wv.y = u.y * __fdividef(n.y * 1.5f, n.y + 1.5f);
            wv.z = u.z * __fdividef(n.z * 1.5f, n.z + 1.5f);
            wv.w = u.w * __fdividef(n.w * 1.5f, n.w + 1.5f);

            acc.x += wv.x * e0.x + wv.y * e1.x + wv.z * e2.x + wv.w * e3.x;
            acc.y += wv.x * e0.y + wv.y * e1.y + wv.z * e2.y + wv.w * e3.y;
            acc.z += wv.x * e0.z + wv.y * e1.z + wv.z * e2.z + wv.w * e3.z;
            acc.w += wv.x * e0.w + wv.y * e1.w + wv.z * e2.w + wv.w * e3.w;
        }
    }

    if (active) {
        *reinterpret_cast<float4*>(out + (long)r * TOTAL + c) = acc;
    }
}

extern "C" void kernel_launch(void* const* d_in, const int* in_sizes, int n_in,
                              void* d_out, int out_size) {
    // Inputs (metadata order): hs (unused), U, neff, Ey
    const float* U    = (const float*)d_in[1];
    const float* neff = (const float*)d_in[2];
    const float* Ey   = (const float*)d_in[3];
    float* out = (float*)d_out;

    dim3 block(32, 4);
    dim3 grid((TOTAL + 127) / 128, TOTAL / 4);   // (10, 296)
    gather_en_kernel<<<grid, block>>>(Ey, U, neff, out);
}